// round 7
// baseline (speedup 1.0000x reference)
#include <cuda_runtime.h>

// ---------------------------------------------------------------------------
// WTConv2d fused: 3-level Haar DWT -> 3x3 conv (128->128) -> inverse DWT + bias
// Fixed shapes: x(8,32,224,224) f32, weight(128,128,3,3) f32, bias(32) f32
// R3: packed fp32x2 FFMA inner loop (2x fp32 rate on sm_103a)
// ---------------------------------------------------------------------------

#define B 8
#define C 32
#define C4 128

typedef unsigned long long u64;

// Scratch (device globals; no allocation allowed)
__device__ float g_sub0[8 * 128 * 112 * 112];
__device__ float g_y0[8 * 128 * 112 * 112];
__device__ float g_sub1[8 * 128 * 56 * 56];
__device__ float g_y1[8 * 128 * 56 * 56];
__device__ float g_sub2[8 * 128 * 28 * 28];
__device__ float g_y2[8 * 128 * 28 * 28];
__device__ float g_ll1[8 * 32 * 56 * 56];
__device__ float g_ll0[8 * 32 * 112 * 112];
// weights transposed + duplicated: [ic][tap][oc][2] so lanes do one LDG.64
__device__ float g_wT2[128 * 9 * 128 * 2];

// ---------------------------------------------------------------------------
__device__ __forceinline__ u64 pk(float lo, float hi) {
    u64 r; asm("mov.b64 %0,{%1,%2};" : "=l"(r) : "f"(lo), "f"(hi)); return r;
}
__device__ __forceinline__ void upk(u64 v, float& lo, float& hi) {
    asm("mov.b64 {%0,%1},%2;" : "=f"(lo), "=f"(hi) : "l"(v));
}
__device__ __forceinline__ void fma2(u64& d, u64 a, u64 b) {
    asm("fma.rn.f32x2 %0,%1,%2,%0;" : "+l"(d) : "l"(a), "l"(b));
}

// ---------------------------------------------------------------------------
// Weight transpose: (oc, ic, ky, kx) -> [ic][tap][oc] duplicated x2
// ---------------------------------------------------------------------------
__global__ void transpose_w_kernel(const float* __restrict__ w) {
    int idx = blockIdx.x * blockDim.x + threadIdx.x;
    if (idx >= 128 * 128 * 9) return;
    int oc = idx / (128 * 9);
    int r = idx % (128 * 9);
    int ic = r / 9;
    int tap = r % 9;
    float v = w[idx];
    int o = ((ic * 9 + tap) * 128 + oc) * 2;
    g_wT2[o] = v;
    g_wT2[o + 1] = v;
}

// ---------------------------------------------------------------------------
// Haar DWT
// ---------------------------------------------------------------------------
__global__ void dwt_kernel(const float* __restrict__ in, float* __restrict__ out,
                           int cmult, int Ctot, int H, int W) {
    int h = H >> 1, w = W >> 1;
    long idx = (long)blockIdx.x * blockDim.x + threadIdx.x;
    long total = (long)B * C * h * w;
    if (idx >= total) return;
    int j = idx % w;
    long t = idx / w;
    int i = t % h; t /= h;
    int c = t % C;
    int b = t / C;

    const float* p = in + (((long)b * Ctot + (long)c * cmult) * H + 2 * i) * W + 2 * j;
    float a = p[0], bb = p[1], cc = p[W], dd = p[W + 1];

    long plane = (long)h * w;
    float* o = out + (((long)b * C4 + c * 4) * h + i) * w + j;
    o[0]         = (a + bb + cc + dd) * 0.5f;
    o[plane]     = (a - bb + cc - dd) * 0.5f;
    o[2 * plane] = (a + bb - cc - dd) * 0.5f;
    o[3 * plane] = (a - bb - cc + dd) * 0.5f;
}

// ---------------------------------------------------------------------------
// Direct 3x3 conv, 128ch -> 128ch, pad 1, stride 1. Packed f32x2 math.
// Block: 32 oc x 8 rows x 8 cols, 256 threads. Input tile in smem (2x 64ic).
// ---------------------------------------------------------------------------
__global__ void __launch_bounds__(256) conv3x3_kernel(
    const float* __restrict__ in, float* __restrict__ out, int H, int W) {
    __shared__ float s_in[64 * 100];  // 25.6 KB

    int tx = threadIdx.x;
    int x0 = blockIdx.x * 8;
    int y0 = blockIdx.y * 8;
    int bz = blockIdx.z;       // b*4 + ocg
    int b = bz >> 2;
    int ocg = bz & 3;
    int lane = tx & 31;
    int row = tx >> 5;         // 0..7
    int oc = ocg * 32 + lane;

    u64 acc[4];
#pragma unroll
    for (int i = 0; i < 4; i++) acc[i] = pk(0.f, 0.f);

    const float* inb = in + (long)b * 128 * H * W;
    const u64* w64 = (const u64*)g_wT2;

    for (int icc = 0; icc < 2; icc++) {
        __syncthreads();
        for (int k = tx; k < 6400; k += 256) {
            int ic = k / 100;
            int r = k % 100;
            int yy = r / 10, xx = r % 10;
            int gy = y0 - 1 + yy, gx = x0 - 1 + xx;
            float v = 0.f;
            if (gy >= 0 && gy < H && gx >= 0 && gx < W)
                v = inb[((long)(icc * 64 + ic) * H + gy) * W + gx];
            s_in[k] = v;
        }
        __syncthreads();

        // lane weight base: [(icc*64+ic)*9 + tap]*128 + oc
        const u64* wb = w64 + ((long)(icc * 64) * 9) * 128 + oc;
#pragma unroll 1
        for (int ic = 0; ic < 64; ic++) {
            const float2* srow = (const float2*)(s_in + ic * 100 + row * 10);
            const u64* wic = wb + (long)ic * 9 * 128;
#pragma unroll
            for (int ky = 0; ky < 3; ky++) {
                float2 e0 = srow[ky * 5 + 0];
                float2 e1 = srow[ky * 5 + 1];
                float2 e2 = srow[ky * 5 + 2];
                float2 e3 = srow[ky * 5 + 3];
                float2 e4 = srow[ky * 5 + 4];
                u64 E0 = pk(e0.x, e0.y);
                u64 E1 = pk(e1.x, e1.y);
                u64 E2 = pk(e2.x, e2.y);
                u64 E3 = pk(e3.x, e3.y);
                u64 E4 = pk(e4.x, e4.y);
                u64 O0 = pk(e0.y, e1.x);
                u64 O1 = pk(e1.y, e2.x);
                u64 O2 = pk(e2.y, e3.x);
                u64 O3 = pk(e3.y, e4.x);

                u64 w0 = __ldg(wic + (ky * 3 + 0) * 128);
                u64 w1 = __ldg(wic + (ky * 3 + 1) * 128);
                u64 w2 = __ldg(wic + (ky * 3 + 2) * 128);

                fma2(acc[0], E0, w0); fma2(acc[1], E1, w0);
                fma2(acc[2], E2, w0); fma2(acc[3], E3, w0);

                fma2(acc[0], O0, w1); fma2(acc[1], O1, w1);
                fma2(acc[2], O2, w1); fma2(acc[3], O3, w1);

                fma2(acc[0], E1, w2); fma2(acc[1], E2, w2);
                fma2(acc[2], E3, w2); fma2(acc[3], E4, w2);
            }
        }
    }

    int oy = y0 + row;
    if (oy < H) {
        float* op = out + (((long)b * 128 + oc) * H + oy) * W + x0;
        float r[8];
#pragma unroll
        for (int p = 0; p < 4; p++) upk(acc[p], r[2 * p], r[2 * p + 1]);
        if (x0 + 8 <= W) {
#pragma unroll
            for (int x = 0; x < 8; x++) op[x] = r[x];
        } else {
#pragma unroll
            for (int x = 0; x < 8; x++)
                if (x0 + x < W) op[x] = r[x];
        }
    }
}

// ---------------------------------------------------------------------------
// Inverse Haar DWT (+ optional LL add, + optional bias)
// ---------------------------------------------------------------------------
__global__ void idwt_kernel(const float* __restrict__ y, const float* __restrict__ ll_add,
                            float* __restrict__ out, const float* __restrict__ bias,
                            int h, int w) {
    long idx = (long)blockIdx.x * blockDim.x + threadIdx.x;
    long total = (long)B * C * h * w;
    if (idx >= total) return;
    int j = idx % w;
    long t = idx / w;
    int i = t % h; t /= h;
    int c = t % C;
    int b = t / C;

    long plane = (long)h * w;
    const float* p = y + (((long)b * C4 + c * 4) * h + i) * w + j;
    float ll = p[0];
    if (ll_add) ll += ll_add[(((long)b * C + c) * h + i) * w + j];
    float lh = p[plane], hl = p[2 * plane], hh = p[3 * plane];

    const float s = 0.5f;
    float a  = (ll + lh + hl + hh) * s;
    float bb = (ll - lh + hl - hh) * s;
    float cc = (ll + lh - hl - hh) * s;
    float dd = (ll - lh - hl + hh) * s;

    float bv = bias ? bias[c] : 0.f;
    int W2 = 2 * w;
    float* o = out + (((long)b * C + c) * (2 * h) + 2 * i) * W2 + 2 * j;
    o[0] = a + bv;
    o[1] = bb + bv;
    o[W2] = cc + bv;
    o[W2 + 1] = dd + bv;
}

// ---------------------------------------------------------------------------
extern "C" void kernel_launch(void* const* d_in, const int* in_sizes, int n_in,
                              void* d_out, int out_size) {
    const float* x = (const float*)d_in[0];
    const float* weight = (const float*)d_in[1];
    const float* bias = (const float*)d_in[2];
    float* out = (float*)d_out;

    float *sub0, *y0, *sub1, *y1, *sub2, *y2, *ll1, *ll0;
    cudaGetSymbolAddress((void**)&sub0, g_sub0);
    cudaGetSymbolAddress((void**)&y0, g_y0);
    cudaGetSymbolAddress((void**)&sub1, g_sub1);
    cudaGetSymbolAddress((void**)&y1, g_y1);
    cudaGetSymbolAddress((void**)&sub2, g_sub2);
    cudaGetSymbolAddress((void**)&y2, g_y2);
    cudaGetSymbolAddress((void**)&ll1, g_ll1);
    cudaGetSymbolAddress((void**)&ll0, g_ll0);

    transpose_w_kernel<<<(128 * 128 * 9 + 255) / 256, 256>>>(weight);

    {
        long tot = (long)B * C * 112 * 112;
        dwt_kernel<<<(unsigned)((tot + 255) / 256), 256>>>(x, sub0, 1, 32, 224, 224);
        conv3x3_kernel<<<dim3(14, 14, B * 4), 256>>>(sub0, y0, 112, 112);
    }
    {
        long tot = (long)B * C * 56 * 56;
        dwt_kernel<<<(unsigned)((tot + 255) / 256), 256>>>(sub0, sub1, 4, 128, 112, 112);
        conv3x3_kernel<<<dim3(7, 7, B * 4), 256>>>(sub1, y1, 56, 56);
    }
    {
        long tot = (long)B * C * 28 * 28;
        dwt_kernel<<<(unsigned)((tot + 255) / 256), 256>>>(sub1, sub2, 4, 128, 56, 56);
        conv3x3_kernel<<<dim3(4, 4, B * 4), 256>>>(sub2, y2, 28, 28);
    }

    {
        long tot = (long)B * C * 28 * 28;
        idwt_kernel<<<(unsigned)((tot + 255) / 256), 256>>>(y2, nullptr, ll1, nullptr, 28, 28);
    }
    {
        long tot = (long)B * C * 56 * 56;
        idwt_kernel<<<(unsigned)((tot + 255) / 256), 256>>>(y1, ll1, ll0, nullptr, 56, 56);
    }
    {
        long tot = (long)B * C * 112 * 112;
        idwt_kernel<<<(unsigned)((tot + 255) / 256), 256>>>(y0, ll0, out, bias, 112, 112);
    }
}

// round 13
// speedup vs baseline: 3.6481x; 3.6481x over previous
#include <cuda_runtime.h>
#include <cuda_bf16.h>
#include <cstdint>

// ---------------------------------------------------------------------------
// WTConv2d fused — warp-level bf16 mma.sync implicit GEMM (plain sm_103 PTX).
// x(8,32,224,224) f32, weight(128,128,3,3) f32, bias(32) f32 -> out f32.
// Per level: DWT+pack (channels-last bf16 hi/lo, zero halo) -> implicit GEMM
// 3x3 conv (9 taps x 2 ic-planes, 3 bf16 split terms, fp32 accum in regs)
// -> NCHW y. Then inverse-DWT cascade (fp32) + bias.
// R13: fix B-operand orientation (ldmatrix WITHOUT .trans).
// ---------------------------------------------------------------------------

#define Bn 8
#define Cn 32
#define C4 128

typedef unsigned int u32;
typedef unsigned long long u64;

// ------------------------------ scratch -----------------------------------
__device__ __align__(16) float g_y0[8 * 128 * 112 * 112];
__device__ __align__(16) float g_y1[8 * 128 * 56 * 56];
__device__ __align__(16) float g_y2[8 * 128 * 28 * 28];
__device__ __align__(16) float g_LL0[8 * 32 * 112 * 112];
__device__ __align__(16) float g_LL1[8 * 32 * 56 * 56];
__device__ __align__(16) float g_LL2[8 * 32 * 28 * 28];
__device__ __align__(16) float g_li1[8 * 32 * 56 * 56];
__device__ __align__(16) float g_li0[8 * 32 * 112 * 112];
__device__ __align__(256) __nv_bfloat16 g_xh0[8 * 114 * 114 * 128];
__device__ __align__(256) __nv_bfloat16 g_xl0[8 * 114 * 114 * 128];
__device__ __align__(256) __nv_bfloat16 g_xh1[8 * 58 * 58 * 128];
__device__ __align__(256) __nv_bfloat16 g_xl1[8 * 58 * 58 * 128];
__device__ __align__(256) __nv_bfloat16 g_xh2[8 * 30 * 30 * 128];
__device__ __align__(256) __nv_bfloat16 g_xl2[8 * 30 * 30 * 128];
// weights in mma A-fragment order:
// [chunk(36) = (tap*2+plane)*2+term][ocblk(8)][lane(32)][ks(4)][reg(4)] u32(bf16x2)
__device__ __align__(16) u32 g_wfrag[36 * 8 * 32 * 16];

// ------------------------------ PTX helpers --------------------------------
__device__ __forceinline__ u32 smem_u32(const void* p) {
    u32 a;
    asm("{ .reg .u64 t; cvta.to.shared.u64 t, %1; cvt.u32.u64 %0, t; }"
        : "=r"(a) : "l"(p));
    return a;
}
#define SWZ(o) ((o) ^ (((o) >> 3) & 0x70))

__device__ __forceinline__ void cp16(u32 dst, const void* src) {
    asm volatile("cp.async.cg.shared.global [%0], [%1], 16;\n"
                 :: "r"(dst), "l"(src) : "memory");
}
__device__ __forceinline__ void cp_commit() {
    asm volatile("cp.async.commit_group;" ::: "memory");
}
template <int N>
__device__ __forceinline__ void cp_wait() {
    asm volatile("cp.async.wait_group %0;" :: "n"(N) : "memory");
}
// NON-transposed: smem rows = pixels(N), cols = ic(K) contiguous.
// Fragment: lane l -> row l/4 (pixel), 4-byte word (l%4) (two consecutive ic).
// This matches the mma.m16n8k16 ".col" B fragment (n = l/4, k = (l%4)*2,+1).
__device__ __forceinline__ void ldsm4(u32* r, u32 a) {
    asm volatile("ldmatrix.sync.aligned.m8n8.x4.shared.b16 {%0,%1,%2,%3}, [%4];"
                 : "=r"(r[0]), "=r"(r[1]), "=r"(r[2]), "=r"(r[3]) : "r"(a));
}
__device__ __forceinline__ void mma16816(float* d, uint4 a, u32 b0, u32 b1) {
    asm volatile(
        "mma.sync.aligned.m16n8k16.row.col.f32.bf16.bf16.f32 "
        "{%0,%1,%2,%3}, {%4,%5,%6,%7}, {%8,%9}, {%0,%1,%2,%3};"
        : "+f"(d[0]), "+f"(d[1]), "+f"(d[2]), "+f"(d[3])
        : "r"(a.x), "r"(a.y), "r"(a.z), "r"(a.w), "r"(b0), "r"(b1));
}

// ------------------------- weight prep kernel ------------------------------
// Emits bf16 hi/lo weights directly in per-thread mma A-fragment order.
// u32 idx -> ri=idx&3, ks=(idx>>2)&3, lane=(idx>>4)&31, blk=(idx>>9)&7, chunk=idx>>12
// chunk = (tap*2+plane)*2+term.  oc = blk*16 + (ri&1)*8 + (lane>>2)
// ic = ks*16 + ((ri>>1)&1)*8 + (lane&3)*2  (two consecutive ic packed)
__global__ void wprep_kernel(const float* __restrict__ w) {
    int idx = blockIdx.x * 256 + threadIdx.x;
    if (idx >= 36 * 8 * 32 * 16) return;
    int ri = idx & 3;
    int ks = (idx >> 2) & 3;
    int lane = (idx >> 4) & 31;
    int blk = (idx >> 9) & 7;
    int chunk = idx >> 12;
    int term = chunk & 1, plane = (chunk >> 1) & 1, tap = chunk >> 2;
    int oc = blk * 16 + (ri & 1) * 8 + (lane >> 2);
    int ic = ks * 16 + ((ri >> 1) & 1) * 8 + (lane & 3) * 2;
    u32 pack = 0;
#pragma unroll
    for (int e = 0; e < 2; e++) {
        float v = w[((oc * 128) + plane * 64 + ic + e) * 9 + tap];
        __nv_bfloat16 hi = __float2bfloat16(v);
        __nv_bfloat16 o = term ? __float2bfloat16(v - __bfloat162float(hi)) : hi;
        pack |= (u32)__bfloat16_as_ushort(o) << (16 * e);
    }
    g_wfrag[idx] = pack;
}

// ------------------------- DWT + pack kernel -------------------------------
__global__ void dwtpack_kernel(const float* __restrict__ in,
                               __nv_bfloat16* __restrict__ xh,
                               __nv_bfloat16* __restrict__ xl,
                               float* __restrict__ llout, int h, int w) {
    long idx = (long)blockIdx.x * 256 + threadIdx.x;
    long total = (long)Bn * Cn * h * w;
    if (idx >= total) return;
    int j = idx % w;
    long t = idx / w;
    int i = t % h; t /= h;
    int c = t % Cn;
    int b = t / Cn;

    const float* p = in + (((long)(b * Cn + c)) * (2 * h) + 2 * i) * (2 * w) + 2 * j;
    float a = p[0], bv = p[1], cv = p[2 * w], dv = p[2 * w + 1];
    float ll = (a + bv + cv + dv) * 0.5f;
    float lh = (a - bv + cv - dv) * 0.5f;
    float hl = (a + bv - cv - dv) * 0.5f;
    float hh = (a - bv - cv + dv) * 0.5f;
    llout[idx] = ll;

    __nv_bfloat16 h0 = __float2bfloat16(ll), h1 = __float2bfloat16(lh);
    __nv_bfloat16 h2 = __float2bfloat16(hl), h3 = __float2bfloat16(hh);
    __nv_bfloat16 l0 = __float2bfloat16(ll - __bfloat162float(h0));
    __nv_bfloat16 l1 = __float2bfloat16(lh - __bfloat162float(h1));
    __nv_bfloat16 l2 = __float2bfloat16(hl - __bfloat162float(h2));
    __nv_bfloat16 l3 = __float2bfloat16(hh - __bfloat162float(h3));

    long px = ((long)b * (h + 2) + i + 1) * (w + 2) + j + 1;
    long off = px * 128 + 4 * c;
    uint2 vh, vl;
    vh.x = (u32)__bfloat16_as_ushort(h0) | ((u32)__bfloat16_as_ushort(h1) << 16);
    vh.y = (u32)__bfloat16_as_ushort(h2) | ((u32)__bfloat16_as_ushort(h3) << 16);
    vl.x = (u32)__bfloat16_as_ushort(l0) | ((u32)__bfloat16_as_ushort(l1) << 16);
    vl.y = (u32)__bfloat16_as_ushort(l2) | ((u32)__bfloat16_as_ushort(l3) << 16);
    *(uint2*)(xh + off) = vh;
    *(uint2*)(xl + off) = vl;
}

// ------------------------- zero-border kernel ------------------------------
__global__ void zb_kernel(__nv_bfloat16* __restrict__ xh,
                          __nv_bfloat16* __restrict__ xl, int h, int w) {
    int P = 2 * (w + 2) + 2 * h;
    int idx = blockIdx.x * 256 + threadIdx.x;
    int total = Bn * P * 16;
    if (idx >= total) return;
    int q = idx & 15;
    int pp = (idx >> 4) % P;
    int b = idx / (16 * P);
    int y, x;
    if (pp < w + 2) { y = 0; x = pp; }
    else if (pp < 2 * (w + 2)) { y = h + 1; x = pp - (w + 2); }
    else if (pp < 2 * (w + 2) + h) { y = pp - 2 * (w + 2) + 1; x = 0; }
    else { y = pp - 2 * (w + 2) - h + 1; x = w + 1; }
    long off = (((long)b * (h + 2) + y) * (w + 2) + x) * 128 + q * 8;
    uint4 z = {0, 0, 0, 0};
    *(uint4*)(xh + off) = z;
    *(uint4*)(xl + off) = z;
}

// ------------------------- mma.sync conv kernel ----------------------------
// CTA: 128 oc x NT=W*RPT pixels. 8 warps: MW in M, 8/MW in N.
// Per group g=(tap,plane): B hi/lo tiles [NT pix][64 ic] swizzled in smem
// (double-buffered cp.async); A fragments LDG.128 from g_wfrag (L1-hot).
// 3 split terms: Ah*Bh + Ah*Bl + Al*Bh, fp32 accum in registers.
template <int W, int RPT, int MW>
__global__ void __launch_bounds__(256, 1) conv_mma_kernel(
    const __nv_bfloat16* __restrict__ xh, const __nv_bfloat16* __restrict__ xl,
    float* __restrict__ y) {
    constexpr int H = W;
    constexpr int WP = W + 2;
    constexpr int NT = W * RPT;
    constexpr int BT = NT * 128;          // bytes per term tile
    constexpr int NW = 8 / MW;
    constexpr int NPW = NT / NW;          // pixels per warp
    constexpr int NB8 = NPW / 8;
    constexpr int NB16 = NB8 / 2;
    constexpr int MF = 8 / MW;            // m16 fragments per warp
    constexpr int NLD = (NT * 8 + 255) / 256;
    static_assert(NB16 * 2 == NB8, "NB8 must be even");

    extern __shared__ char smem[];
    u32 sb = smem_u32(smem);
    u32 bufs = (sb + 1023) & ~1023u;

    int tid = threadIdx.x;
    int lane = tid & 31;
    int wid = tid >> 5;
    int b = blockIdx.y;
    int y0 = blockIdx.x * RPT;
    int warpM = wid & (MW - 1);
    int warpN = wid / MW;
    int ocb = warpM * (128 / MW);
    int n_base = warpN * NPW;
    int gid = lane >> 2, tig = lane & 3;

    // cp.async precompute (B tiles)
    int pixB[NLD];
    u32 dstB[NLD];
#pragma unroll
    for (int k = 0; k < NLD; k++) {
        int s = tid + 256 * k;
        if (s < NT * 8) {
            int n = s >> 3, q = s & 7;
            int r = n / W, cx = n % W;
            pixB[k] = (((b * (H + 2)) + y0 + r) * WP + cx) * 128 + q * 8;
            dstB[k] = SWZ((u32)(s * 16));
        } else { pixB[k] = -1; dstB[k] = 0; }
    }

    auto load_group = [&](int g) {
        int tap = g >> 1, plane = g & 1;
        int dy = tap / 3, dx = tap % 3;
        int shift = (dy * WP + dx) * 128 + plane * 64;
        u32 base = bufs + (u32)(g & 1) * (2 * BT);
#pragma unroll
        for (int k = 0; k < NLD; k++)
            if (pixB[k] >= 0) {
                cp16(base + dstB[k], xh + pixB[k] + shift);
                cp16(base + BT + dstB[k], xl + pixB[k] + shift);
            }
        cp_commit();
    };

    // B ldmatrix per-thread addressing
    int tileIdx = lane >> 3, lane7 = lane & 7;
    int pixlane = n_base + ((tileIdx >> 1) << 3) + lane7;
    u32 kmask = (u32)((pixlane & 7) << 4);
    u32 bB = (u32)(pixlane * 128);
    u32 kb0 = (u32)((tileIdx & 1) << 4);

    float acc[MF][NB8][4];
#pragma unroll
    for (int a = 0; a < MF; a++)
#pragma unroll
        for (int n = 0; n < NB8; n++)
#pragma unroll
            for (int i = 0; i < 4; i++) acc[a][n][i] = 0.f;

    load_group(0);

#pragma unroll 1
    for (int g = 0; g < 18; g++) {
        if (g < 17) { load_group(g + 1); cp_wait<1>(); }
        else cp_wait<0>();
        __syncthreads();
        u32 base = bufs + (u32)(g & 1) * (2 * BT);
        const uint4* ap = ((const uint4*)g_wfrag) + (size_t)(g * 2) * 1024;
#pragma unroll
        for (int ks = 0; ks < 4; ks++) {
            uint4 A[2][MF];
#pragma unroll
            for (int t = 0; t < 2; t++)
#pragma unroll
                for (int mf = 0; mf < MF; mf++)
                    A[t][mf] = __ldg(ap + (size_t)t * 1024 +
                                     (warpM * MF + mf) * 128 + lane * 4 + ks);
            u32 kb = (kb0 + (u32)(ks * 32)) ^ kmask;
#pragma unroll
            for (int nb = 0; nb < NB16; nb++) {
                u32 addr = base + bB + (u32)(nb * 2048) + kb;
                u32 bh[4], bl[4];
                ldsm4(bh, addr);
                ldsm4(bl, addr + BT);
#pragma unroll
                for (int mf = 0; mf < MF; mf++) {
                    mma16816(acc[mf][2 * nb],     A[0][mf], bh[0], bh[1]);
                    mma16816(acc[mf][2 * nb + 1], A[0][mf], bh[2], bh[3]);
                    mma16816(acc[mf][2 * nb],     A[0][mf], bl[0], bl[1]);
                    mma16816(acc[mf][2 * nb + 1], A[0][mf], bl[2], bl[3]);
                    mma16816(acc[mf][2 * nb],     A[1][mf], bh[0], bh[1]);
                    mma16816(acc[mf][2 * nb + 1], A[1][mf], bh[2], bh[3]);
                }
            }
        }
        if (g < 17) __syncthreads();
    }

    // epilogue: D fragment (c0,c1: row=gid, cols tig*2,+1; c2,c3: row=gid+8)
    float* yb = y + (size_t)(b * 128) * H * W;
#pragma unroll
    for (int mf = 0; mf < MF; mf++) {
        int oc0 = ocb + mf * 16 + gid;
#pragma unroll
        for (int nb = 0; nb < NB8; nb++) {
            int p = n_base + nb * 8 + tig * 2;
            int pr = p / W, pc = p % W;
            float* o0 = yb + (size_t)oc0 * H * W + (y0 + pr) * W + pc;
            float2 v0 = {acc[mf][nb][0], acc[mf][nb][1]};
            float2 v1 = {acc[mf][nb][2], acc[mf][nb][3]};
            *(float2*)o0 = v0;
            *(float2*)(o0 + 8 * H * W) = v1;
        }
    }
}

// ------------------------- inverse DWT (verified) --------------------------
__global__ void idwt_kernel(const float* __restrict__ y, const float* __restrict__ ll_add,
                            float* __restrict__ out, const float* __restrict__ bias,
                            int h, int w) {
    long idx = (long)blockIdx.x * blockDim.x + threadIdx.x;
    long total = (long)Bn * Cn * h * w;
    if (idx >= total) return;
    int j = idx % w;
    long t = idx / w;
    int i = t % h; t /= h;
    int c = t % Cn;
    int b = t / Cn;

    long plane = (long)h * w;
    const float* p = y + (((long)b * C4 + c * 4) * h + i) * w + j;
    float ll = p[0];
    if (ll_add) ll += ll_add[(((long)b * Cn + c) * h + i) * w + j];
    float lh = p[plane], hl = p[2 * plane], hh = p[3 * plane];

    const float s = 0.5f;
    float a  = (ll + lh + hl + hh) * s;
    float bb = (ll - lh + hl - hh) * s;
    float cc = (ll + lh - hl - hh) * s;
    float dd = (ll - lh - hl + hh) * s;

    float bv = bias ? bias[c] : 0.f;
    int W2 = 2 * w;
    float* o = out + (((long)b * Cn + c) * (2 * h) + 2 * i) * W2 + 2 * j;
    o[0] = a + bv;
    o[1] = bb + bv;
    o[W2] = cc + bv;
    o[W2 + 1] = dd + bv;
}

// ---------------------------------------------------------------------------
extern "C" void kernel_launch(void* const* d_in, const int* in_sizes, int n_in,
                              void* d_out, int out_size) {
    const float* x = (const float*)d_in[0];
    const float* weight = (const float*)d_in[1];
    const float* bias = (const float*)d_in[2];
    float* out = (float*)d_out;

    float *y0, *y1, *y2, *LL0, *LL1, *LL2, *li1, *li0;
    __nv_bfloat16 *xh0, *xl0, *xh1, *xl1, *xh2, *xl2;
    cudaGetSymbolAddress((void**)&y0, g_y0);
    cudaGetSymbolAddress((void**)&y1, g_y1);
    cudaGetSymbolAddress((void**)&y2, g_y2);
    cudaGetSymbolAddress((void**)&LL0, g_LL0);
    cudaGetSymbolAddress((void**)&LL1, g_LL1);
    cudaGetSymbolAddress((void**)&LL2, g_LL2);
    cudaGetSymbolAddress((void**)&li1, g_li1);
    cudaGetSymbolAddress((void**)&li0, g_li0);
    cudaGetSymbolAddress((void**)&xh0, g_xh0);
    cudaGetSymbolAddress((void**)&xl0, g_xl0);
    cudaGetSymbolAddress((void**)&xh1, g_xh1);
    cudaGetSymbolAddress((void**)&xl1, g_xl1);
    cudaGetSymbolAddress((void**)&xh2, g_xh2);
    cudaGetSymbolAddress((void**)&xl2, g_xl2);

    constexpr int SM01 = 1024 + 4 * 224 * 128;  // 115712
    constexpr int SM2  = 1024 + 4 * 112 * 128;  // 58368
    cudaFuncSetAttribute(conv_mma_kernel<112, 2, 4>,
                         cudaFuncAttributeMaxDynamicSharedMemorySize, SM01);
    cudaFuncSetAttribute(conv_mma_kernel<56, 4, 4>,
                         cudaFuncAttributeMaxDynamicSharedMemorySize, SM01);
    cudaFuncSetAttribute(conv_mma_kernel<28, 4, 8>,
                         cudaFuncAttributeMaxDynamicSharedMemorySize, SM2);

    wprep_kernel<<<(36 * 8 * 32 * 16 + 255) / 256, 256>>>(weight);

    // level 0
    {
        long tot = (long)Bn * Cn * 112 * 112;
        dwtpack_kernel<<<(unsigned)((tot + 255) / 256), 256>>>(x, xh0, xl0, LL0, 112, 112);
        int P = 2 * 114 + 2 * 112;
        zb_kernel<<<(Bn * P * 16 + 255) / 256, 256>>>(xh0, xl0, 112, 112);
        conv_mma_kernel<112, 2, 4><<<dim3(56, 8), 256, SM01>>>(xh0, xl0, y0);
    }
    // level 1
    {
        long tot = (long)Bn * Cn * 56 * 56;
        dwtpack_kernel<<<(unsigned)((tot + 255) / 256), 256>>>(LL0, xh1, xl1, LL1, 56, 56);
        int P = 2 * 58 + 2 * 56;
        zb_kernel<<<(Bn * P * 16 + 255) / 256, 256>>>(xh1, xl1, 56, 56);
        conv_mma_kernel<56, 4, 4><<<dim3(14, 8), 256, SM01>>>(xh1, xl1, y1);
    }
    // level 2
    {
        long tot = (long)Bn * Cn * 28 * 28;
        dwtpack_kernel<<<(unsigned)((tot + 255) / 256), 256>>>(LL1, xh2, xl2, LL2, 28, 28);
        int P = 2 * 30 + 2 * 28;
        zb_kernel<<<(Bn * P * 16 + 255) / 256, 256>>>(xh2, xl2, 28, 28);
        conv_mma_kernel<28, 4, 8><<<dim3(7, 8), 256, SM2>>>(xh2, xl2, y2);
    }

    // inverse cascade
    {
        long tot = (long)Bn * Cn * 28 * 28;
        idwt_kernel<<<(unsigned)((tot + 255) / 256), 256>>>(y2, nullptr, li1, nullptr, 28, 28);
    }
    {
        long tot = (long)Bn * Cn * 56 * 56;
        idwt_kernel<<<(unsigned)((tot + 255) / 256), 256>>>(y1, li1, li0, nullptr, 56, 56);
    }
    {
        long tot = (long)Bn * Cn * 112 * 112;
        idwt_kernel<<<(unsigned)((tot + 255) / 256), 256>>>(y0, li0, out, bias, 112, 112);
    }
}